// round 5
// baseline (speedup 1.0000x reference)
#include <cuda_runtime.h>

#define NB   128          // blocks, all co-resident (128 <= 148 SMs)
#define NT   256
#define NCLS 16
#define DIM  128
#define NR   8192
#define RPB  (NR / NB)    // 64 rows per block
#define HP   (RPB / 2)    // 32 feature values held per thread
#define GPITCH 132
#define EPS  1e-6
#define MARGIN 10.0
#define SCALE_F 4294967296.0          // 2^32 fixed-point scale for Fsum
#define INV_F   (1.0 / 4294967296.0)
#define SCALE_S 16777216.0            // 2^24 scale for sum-of-squares
#define INV_S   (1.0 / 16777216.0)

// ---- persistent scratch (no allocation allowed) ----
__device__ unsigned long long g_aF[NCLS][DIM];  // fixed-point Fsum accumulators
__device__ unsigned long long g_aS[NCLS];       // fixed-point sum-of-squares
__device__ int      g_aC[NCLS];                 // class counts
__device__ unsigned g_c0, g_c2;                 // monotone barrier counters
__device__ unsigned g_ep[NB * 8];               // per-block epoch (padded, private)
__device__ double   g_bL[NB], g_bV[NB];         // per-block loss/valid partials

__device__ __forceinline__ void spin_until(volatile unsigned* c, unsigned target) {
    while ((int)(*c - target) < 0) __nanosleep(64);
}

__global__ void __launch_bounds__(NT, 1)
fused_contrastive(const float* __restrict__ f, const int* __restrict__ labw,
                  float* __restrict__ out) {
    __shared__ float s1[2][NCLS][DIM];   // phase1 Fsum partials | later: Fs copy (flat, first half)
    __shared__ float s2[2][NCLS][DIM];   // phase1 sq partials
    __shared__ float sG[NCLS][GPITCH];
    __shared__ int   sLab[RPB];
    __shared__ float sTot[DIM];
    __shared__ float sAl[NCLS], sBe[NCLS], sAv[NCLS], sBv[NCLS], sSq[NCLS];
    __shared__ int   sCt[NCLS];
    __shared__ float sPS[NCLS][8];
    __shared__ int   sPC[NCLS][8];
    __shared__ float sRP[RPB][4], sRQ[RPB][4];
    __shared__ float sWL[2], sWV[2];
    __shared__ double sSqTotD;
    __shared__ unsigned sEpoch;
    __shared__ int   sLast;
    __shared__ double rL[NB], rV[NB];

    const int tid  = threadIdx.x;
    const int b    = blockIdx.x;
    const int r0   = b * RPB;
    const int dim  = tid & (DIM - 1);
    const int h    = tid >> 7;
    const int w    = tid >> 5;
    const int lane = tid & 31;

    // ---- ONE dependent DRAM round: features + detect words + BOTH label layouts
    float v[HP];
#pragma unroll
    for (int it = 0; it < HP; ++it)
        v[it] = f[(size_t)(r0 + 2 * it + h) * DIM + dim];
    int l32 = 0, l64 = 0;
    if (tid < RPB) {
        l32 = labw[r0 + tid];
        l64 = labw[(r0 + tid) << 1];
    }
    int acc = labw[2 * tid + 1] | labw[2 * (tid + NT) + 1];
    const int is64 = (__syncthreads_or(acc) == 0);
    if (tid < RPB) sLab[tid] = (is64 ? l64 : l32) & (NCLS - 1);
    for (int i = tid; i < 2 * NCLS * DIM; i += NT) {
        (&s1[0][0][0])[i] = 0.f;
        (&s2[0][0][0])[i] = 0.f;
    }
    __syncthreads();

    // ---------- Phase 1: per-block class partials ------------------------------
#pragma unroll
    for (int it = 0; it < HP; ++it) {
        const int k = sLab[2 * it + h];
        s1[h][k][dim] += v[it];
        s2[h][k][dim] = fmaf(v[it], v[it], s2[h][k][dim]);
    }
    __syncthreads();

    // ---- commit partials via exact fixed-point atomics (spread addresses) -----
    if (tid < DIM) {
#pragma unroll
        for (int k = 0; k < NCLS; ++k) {
            const double p = (double)(s1[0][k][tid] + s1[1][k][tid]);
            atomicAdd(&g_aF[k][tid], (unsigned long long)__double2ll_rn(p * SCALE_F));
        }
    } else {
        const int t = tid - DIM, k = t >> 3, part = t & 7;
        float s = 0.f;
#pragma unroll
        for (int d = 0; d < 16; ++d) {
            const int dd = part * 16 + d;
            s += s2[0][k][dd] + s2[1][k][dd];
        }
        sPS[k][part] = s;
        int c = 0;
#pragma unroll
        for (int r = 0; r < 8; ++r) c += (sLab[part * 8 + r] == k);
        sPC[k][part] = c;
    }
    __syncthreads();
    if (tid < NCLS) {
        float s = 0.f; int c = 0;
#pragma unroll
        for (int p = 0; p < 8; ++p) { s += sPS[tid][p]; c += sPC[tid][p]; }
        atomicAdd(&g_aS[tid], (unsigned long long)__double2ll_rn((double)s * SCALE_S));
        atomicAdd(&g_aC[tid], c);
    }

    // ---------- single global barrier ------------------------------------------
    __threadfence();
    __syncthreads();
    if (tid == 0) {
        const unsigned ep = g_ep[b * 8];     // private: no contention
        g_ep[b * 8] = ep + 1;
        sEpoch = ep;
        atomicAdd(&g_c0, 1u);                // return unused -> REDG
        spin_until(&g_c0, (ep + 1) * NB);
    }
    __syncthreads();
    __threadfence();

    // ---------- every block reads reduced stats, builds constants + G ----------
    for (int i = tid; i < NCLS * DIM; i += NT) {
        const long long a = (long long)__ldcg(&g_aF[0][0] + i);
        (&s1[0][0][0])[i] = (float)((double)a * INV_F);
    }
    if (tid < NCLS) {
        sSq[tid] = (float)((double)(long long)__ldcg(&g_aS[tid]) * INV_S);
        sCt[tid] = __ldcg(&g_aC[tid]);
    }
    __syncthreads();
    if (tid < DIM) {
        float t = 0.f;
#pragma unroll
        for (int k = 0; k < NCLS; ++k) t += s1[0][k][tid];
        sTot[tid] = t;
    } else if (tid == NT - 1) {
        double st = 0.0;
#pragma unroll
        for (int k = 0; k < NCLS; ++k) st += (double)sSq[k];
        sSqTotD = st;
    }
    __syncthreads();
    if (tid < NCLS) {
        const double cnt = (double)sCt[tid];
        const double c   = cnt - 1.0;
        const double Bv  = 1.0 / ((double)NR - c - 1.0 + EPS);
        const double Av  = 1.0 / (c + EPS) + Bv;
        sAv[tid] = (float)Av;
        sBv[tid] = (float)Bv;
        sAl[tid] = (float)(cnt * Av - (double)NR * Bv);
        sBe[tid] = (float)((double)sSq[tid] * Av - sSqTotD * Bv + MARGIN);
    }
    __syncthreads();
    for (int i = tid; i < NCLS * DIM; i += NT) {
        const int k = i >> 7, d = i & (DIM - 1);
        sG[k][d] = sAv[k] * s1[0][k][d] - sBv[k] * sTot[d];
    }
    __syncthreads();

    // ---------- Phase 3: per-row loss using RETAINED registers -----------------
    {
        const int wg = w & 3;
#pragma unroll
        for (int it = 0; it < HP; ++it) {
            const int rloc = 2 * it + h;
            const int k = sLab[rloc];
            float p = v[it] * sG[k][dim];
            float q = v[it] * v[it];
#pragma unroll
            for (int off = 16; off; off >>= 1) {
                p += __shfl_down_sync(0xffffffffu, p, off);
                q += __shfl_down_sync(0xffffffffu, q, off);
            }
            if (lane == 0) { sRP[rloc][wg] = p; sRQ[rloc][wg] = q; }
        }
    }
    __syncthreads();
    {
        float cL = 0.f, cV = 0.f;
        if (tid < RPB) {
            const int k = sLab[tid];
            const float dG = (sRP[tid][0] + sRP[tid][1]) + (sRP[tid][2] + sRP[tid][3]);
            const float sq = (sRQ[tid][0] + sRQ[tid][1]) + (sRQ[tid][2] + sRQ[tid][3]);
            const float loss  = fmaf(sAl[k], sq, sBe[k]) - 2.f * dG;
            const float valid = (sCt[k] > 1) ? 1.f : 0.f;
            cL = fmaxf(loss, 0.f) * valid;
            cV = valid;
        }
        if (tid < 64) {
#pragma unroll
            for (int off = 16; off; off >>= 1) {
                cL += __shfl_down_sync(0xffffffffu, cL, off);
                cV += __shfl_down_sync(0xffffffffu, cV, off);
            }
            if (lane == 0) { sWL[w] = cL; sWV[w] = cV; }
        }
    }
    __syncthreads();

    // ---------- tail: last-arriving block reduces + re-zeroes accumulators -----
    if (tid == 0) {
        g_bL[b] = (double)sWL[0] + (double)sWL[1];
        g_bV[b] = (double)sWV[0] + (double)sWV[1];
        __threadfence();
        const unsigned tk2 = atomicAdd(&g_c2, 1u);   // returning atomic: elect last
        sLast = (tk2 == (sEpoch + 1) * NB - 1u);
    }
    __syncthreads();

    if (sLast) {
        __threadfence();
        // reset accumulators for the next graph replay (all blocks already consumed them)
        for (int i = tid; i < NCLS * DIM; i += NT) (&g_aF[0][0])[i] = 0ull;
        if (tid < NCLS) { g_aS[tid] = 0ull; g_aC[tid] = 0; }
        if (tid < NB) {
            rL[tid] = __ldcg(&g_bL[tid]);
            rV[tid] = __ldcg(&g_bV[tid]);
        }
        __syncthreads();
        for (int off = NB / 2; off; off >>= 1) {
            if (tid < off) { rL[tid] += rL[tid + off]; rV[tid] += rV[tid + off]; }
            __syncthreads();
        }
        if (tid == 0)
            out[0] = (float)(rL[0] / (rV[0] > 1.0 ? rV[0] : 1.0));
    }
}

extern "C" void kernel_launch(void* const* d_in, const int* in_sizes, int n_in,
                              void* d_out, int out_size) {
    const float* f    = (const float*)d_in[0];
    const int*   labw = (const int*)d_in[1];   // int32 or int64 words; detected on-device
    float* out = (float*)d_out;
    fused_contrastive<<<NB, NT>>>(f, labw, out);
}